// round 4
// baseline (speedup 1.0000x reference)
#include <cuda_runtime.h>

#define THREADS   256
#define M         14          // batch rows per CTA
#define DIMV      128         // DATA + AUG
#define WIDTHV    256
#define DATAV     64
#define BATCH     2048
#define TSTEPS    128
#define SUBSTEPS  4
#define MD        (M*DIMV)    // 1792
#define MW        (M*WIDTHV)  // 3584

// ---------------------------------------------------------------------------
// Hidden layer, N=256 outputs. Register tile: TM=14 rows x TN=4 consecutive
// columns per thread. K split by 4 across lanes (kh = tid&3); partials
// all-reduced with a 2-round butterfly shuffle (partners are lane-xor 1,2).
// Weights streamed from L2 via __ldg (each weight read once per CTA per eval);
// activations broadcast from SMEM (8 lanes share each address).
// ---------------------------------------------------------------------------
template<int KDIM>
__device__ __forceinline__ void layer256(const float* __restrict__ in_sm,
                                         float* __restrict__ out_sm,
                                         const float* __restrict__ W,
                                         const float* __restrict__ Bv,
                                         int tid)
{
    const int kh = tid & 3;
    const int j  = (tid >> 2) << 2;   // columns j..j+3
    const int KR = KDIM / 4;          // per-lane K range
    const int k0 = kh * KR;

    float acc[M][4];
#pragma unroll
    for (int m = 0; m < M; ++m)
#pragma unroll
        for (int c = 0; c < 4; ++c) acc[m][c] = 0.0f;

    const float* w0 = W + (size_t)(j + 0) * KDIM + k0;
    const float* w1 = W + (size_t)(j + 1) * KDIM + k0;
    const float* w2 = W + (size_t)(j + 2) * KDIM + k0;
    const float* w3 = W + (size_t)(j + 3) * KDIM + k0;
    const float* vin = in_sm + k0;

#pragma unroll 1
    for (int kk = 0; kk < KR; kk += 4) {
        float4 wa = __ldg((const float4*)(w0 + kk));
        float4 wb = __ldg((const float4*)(w1 + kk));
        float4 wc = __ldg((const float4*)(w2 + kk));
        float4 wd = __ldg((const float4*)(w3 + kk));
#pragma unroll
        for (int m = 0; m < M; ++m) {
            float4 v = *(const float4*)(vin + m * KDIM + kk);
            acc[m][0] = fmaf(v.x, wa.x, acc[m][0]);
            acc[m][0] = fmaf(v.y, wa.y, acc[m][0]);
            acc[m][0] = fmaf(v.z, wa.z, acc[m][0]);
            acc[m][0] = fmaf(v.w, wa.w, acc[m][0]);
            acc[m][1] = fmaf(v.x, wb.x, acc[m][1]);
            acc[m][1] = fmaf(v.y, wb.y, acc[m][1]);
            acc[m][1] = fmaf(v.z, wb.z, acc[m][1]);
            acc[m][1] = fmaf(v.w, wb.w, acc[m][1]);
            acc[m][2] = fmaf(v.x, wc.x, acc[m][2]);
            acc[m][2] = fmaf(v.y, wc.y, acc[m][2]);
            acc[m][2] = fmaf(v.z, wc.z, acc[m][2]);
            acc[m][2] = fmaf(v.w, wc.w, acc[m][2]);
            acc[m][3] = fmaf(v.x, wd.x, acc[m][3]);
            acc[m][3] = fmaf(v.y, wd.y, acc[m][3]);
            acc[m][3] = fmaf(v.z, wd.z, acc[m][3]);
            acc[m][3] = fmaf(v.w, wd.w, acc[m][3]);
        }
    }

    // butterfly all-reduce over the 4 kh lanes (lane bits 0,1)
#pragma unroll
    for (int m = 0; m < M; ++m)
#pragma unroll
        for (int c = 0; c < 4; ++c) {
            float a = acc[m][c];
            a += __shfl_xor_sync(0xffffffffu, a, 1);
            a += __shfl_xor_sync(0xffffffffu, a, 2);
            acc[m][c] = a;
        }

    if (kh == 0) {
        float4 b = __ldg((const float4*)(Bv + j));
#pragma unroll
        for (int m = 0; m < M; ++m) {
            float4 o;
            o.x = fmaxf(acc[m][0] + b.x, 0.0f);
            o.y = fmaxf(acc[m][1] + b.y, 0.0f);
            o.z = fmaxf(acc[m][2] + b.z, 0.0f);
            o.w = fmaxf(acc[m][3] + b.w, 0.0f);
            *(float4*)(out_sm + m * WIDTHV + j) = o;
        }
    }
}

// ---------------------------------------------------------------------------
// Output layer: N=128, K=256, no relu. TN=4, K split by 8 (kh = tid&7),
// 3-round butterfly reduce. Result written fp32 to the k-slot buffer.
// ---------------------------------------------------------------------------
__device__ __forceinline__ void layer_out(const float* __restrict__ h2,
                                          float* __restrict__ outk,
                                          const float* __restrict__ W3,
                                          const float* __restrict__ b3,
                                          int tid)
{
    const int kh = tid & 7;
    const int j  = (tid >> 3) << 2;   // columns j..j+3 in [0,128)
    const int KR = WIDTHV / 8;        // 32
    const int k0 = kh * KR;

    float acc[M][4];
#pragma unroll
    for (int m = 0; m < M; ++m)
#pragma unroll
        for (int c = 0; c < 4; ++c) acc[m][c] = 0.0f;

    const float* w0 = W3 + (size_t)(j + 0) * WIDTHV + k0;
    const float* w1 = W3 + (size_t)(j + 1) * WIDTHV + k0;
    const float* w2 = W3 + (size_t)(j + 2) * WIDTHV + k0;
    const float* w3 = W3 + (size_t)(j + 3) * WIDTHV + k0;
    const float* vin = h2 + k0;

#pragma unroll 1
    for (int kk = 0; kk < KR; kk += 4) {
        float4 wa = __ldg((const float4*)(w0 + kk));
        float4 wb = __ldg((const float4*)(w1 + kk));
        float4 wc = __ldg((const float4*)(w2 + kk));
        float4 wd = __ldg((const float4*)(w3 + kk));
#pragma unroll
        for (int m = 0; m < M; ++m) {
            float4 v = *(const float4*)(vin + m * WIDTHV + kk);
            acc[m][0] = fmaf(v.x, wa.x, acc[m][0]);
            acc[m][0] = fmaf(v.y, wa.y, acc[m][0]);
            acc[m][0] = fmaf(v.z, wa.z, acc[m][0]);
            acc[m][0] = fmaf(v.w, wa.w, acc[m][0]);
            acc[m][1] = fmaf(v.x, wb.x, acc[m][1]);
            acc[m][1] = fmaf(v.y, wb.y, acc[m][1]);
            acc[m][1] = fmaf(v.z, wb.z, acc[m][1]);
            acc[m][1] = fmaf(v.w, wb.w, acc[m][1]);
            acc[m][2] = fmaf(v.x, wc.x, acc[m][2]);
            acc[m][2] = fmaf(v.y, wc.y, acc[m][2]);
            acc[m][2] = fmaf(v.z, wc.z, acc[m][2]);
            acc[m][2] = fmaf(v.w, wc.w, acc[m][2]);
            acc[m][3] = fmaf(v.x, wd.x, acc[m][3]);
            acc[m][3] = fmaf(v.y, wd.y, acc[m][3]);
            acc[m][3] = fmaf(v.z, wd.z, acc[m][3]);
            acc[m][3] = fmaf(v.w, wd.w, acc[m][3]);
        }
    }

    // butterfly all-reduce over the 8 kh lanes (lane bits 0,1,2)
#pragma unroll
    for (int m = 0; m < M; ++m)
#pragma unroll
        for (int c = 0; c < 4; ++c) {
            float a = acc[m][c];
            a += __shfl_xor_sync(0xffffffffu, a, 1);
            a += __shfl_xor_sync(0xffffffffu, a, 2);
            a += __shfl_xor_sync(0xffffffffu, a, 4);
            acc[m][c] = a;
        }

    if (kh == 0) {
        float4 b = __ldg((const float4*)(b3 + j));
#pragma unroll
        for (int m = 0; m < M; ++m) {
            float4 o;
            o.x = acc[m][0] + b.x;
            o.y = acc[m][1] + b.y;
            o.z = acc[m][2] + b.z;
            o.w = acc[m][3] + b.w;
            *(float4*)(outk + m * DIMV + j) = o;
        }
    }
}

// f(y) = W3 * relu(W2 * relu(W1*y + b1) + b2) + b3  -> outk
__device__ __forceinline__ void eval_f(const float* __restrict__ in,
                                       float* __restrict__ outk,
                                       float* __restrict__ h1, float* __restrict__ h2,
                                       const float* W1, const float* b1,
                                       const float* W2, const float* b2,
                                       const float* W3, const float* b3,
                                       int tid)
{
    layer256<DIMV>(in, h1, W1, b1, tid);
    __syncthreads();
    layer256<WIDTHV>(h1, h2, W2, b2, tid);
    __syncthreads();
    layer_out(h2, outk, W3, b3, tid);
    __syncthreads();
}

// dst = y + dt * sum_s c[s] * ks[s]
template<int NS>
__device__ __forceinline__ void combine(float* __restrict__ dst,
                                        const float* __restrict__ y,
                                        const float* __restrict__ ks,
                                        float dt, const float* c, int tid)
{
#pragma unroll
    for (int r = 0; r < MD / THREADS; ++r) {
        int i = tid + r * THREADS;
        float v = y[i];
#pragma unroll
        for (int s = 0; s < NS; ++s)
            v = fmaf(dt * c[s], ks[s * MD + i], v);
        dst[i] = v;
    }
}

__device__ __forceinline__ void save_state(const float* __restrict__ y,
                                           float* __restrict__ out,
                                           int base, int t, int tid)
{
#pragma unroll
    for (int r = 0; r < (M * DATAV + THREADS - 1) / THREADS; ++r) {
        int i = tid + r * THREADS;
        if (i < M * DATAV) {
            int m = i >> 6, c = i & (DATAV - 1);
            int row = base + m;
            if (row < BATCH)
                out[((size_t)t * BATCH + row) * DATAV + c] = y[m * DIMV + c];
        }
    }
}

extern "C" __global__ void __launch_bounds__(THREADS, 1)
anode_kernel(const float* __restrict__ ts, const float* __restrict__ y0,
             const float* __restrict__ W1, const float* __restrict__ b1,
             const float* __restrict__ W2, const float* __restrict__ b2,
             const float* __restrict__ W3, const float* __restrict__ b3,
             float* __restrict__ out, int out_size)
{
    extern __shared__ float sm[];
    float* tssm = sm;                       // 128
    float* y    = sm + 128;                 // MD
    float* ks   = y    + MD;                // 6*MD
    float* ytmp = ks   + 6 * MD;            // MD
    float* h1   = ytmp + MD;                // MW
    float* h2   = h1   + MW;                // MW

    const int tid  = threadIdx.x;
    const int base = blockIdx.x * M;

    if (tid < TSTEPS) tssm[tid] = ts[tid];

    // load batch tile (clamp overhang rows; their output is never written)
#pragma unroll
    for (int r = 0; r < MD / THREADS; ++r) {
        int i = tid + r * THREADS;
        int m = i >> 7, c = i & (DIMV - 1);
        int row = base + m; if (row > BATCH - 1) row = BATCH - 1;
        y[i] = y0[row * DIMV + c];
    }
    __syncthreads();

    save_state(y, out, base, 0, tid);

    // Dopri5 tableau
    const float c2[1] = {0.2f};
    const float c3[2] = {3.f/40.f, 9.f/40.f};
    const float c4[3] = {44.f/45.f, -56.f/15.f, 32.f/9.f};
    const float c5[4] = {19372.f/6561.f, -25360.f/2187.f, 64448.f/6561.f, -212.f/729.f};
    const float c6[5] = {9017.f/3168.f, -355.f/33.f, 46732.f/5247.f, 49.f/176.f, -5103.f/18656.f};
    const float cb[6] = {35.f/384.f, 0.f, 500.f/1113.f, 125.f/192.f, -2187.f/6784.f, 11.f/84.f};

#pragma unroll 1
    for (int t = 1; t < TSTEPS; ++t) {
        float dt = (tssm[t] - tssm[t - 1]) * (1.0f / SUBSTEPS);
#pragma unroll 1
        for (int s = 0; s < SUBSTEPS; ++s) {
            eval_f(y,    ks + 0 * MD, h1, h2, W1, b1, W2, b2, W3, b3, tid);
            combine<1>(ytmp, y, ks, dt, c2, tid);  __syncthreads();
            eval_f(ytmp, ks + 1 * MD, h1, h2, W1, b1, W2, b2, W3, b3, tid);
            combine<2>(ytmp, y, ks, dt, c3, tid);  __syncthreads();
            eval_f(ytmp, ks + 2 * MD, h1, h2, W1, b1, W2, b2, W3, b3, tid);
            combine<3>(ytmp, y, ks, dt, c4, tid);  __syncthreads();
            eval_f(ytmp, ks + 3 * MD, h1, h2, W1, b1, W2, b2, W3, b3, tid);
            combine<4>(ytmp, y, ks, dt, c5, tid);  __syncthreads();
            eval_f(ytmp, ks + 4 * MD, h1, h2, W1, b1, W2, b2, W3, b3, tid);
            combine<5>(ytmp, y, ks, dt, c6, tid);  __syncthreads();
            eval_f(ytmp, ks + 5 * MD, h1, h2, W1, b1, W2, b2, W3, b3, tid);
            combine<6>(y, y, ks, dt, cb, tid);     __syncthreads();
        }
        save_state(y, out, base, t, tid);
    }

    // second reference output: num_steps = (T-1)*SUBSTEPS = 508
    if (blockIdx.x == 0 && tid == 0) {
        const long long TOT = (long long)TSTEPS * BATCH * DATAV;
        for (long long i = TOT; i < (long long)out_size; ++i)
            out[i] = 508.0f;
    }
}

extern "C" void kernel_launch(void* const* d_in, const int* in_sizes, int n_in,
                              void* d_out, int out_size)
{
    const float* ts = (const float*)d_in[0];
    const float* y0 = (const float*)d_in[1];
    const float* W1 = (const float*)d_in[2];
    const float* b1 = (const float*)d_in[3];
    const float* W2 = (const float*)d_in[4];
    const float* b2 = (const float*)d_in[5];
    const float* W3 = (const float*)d_in[6];
    const float* b3 = (const float*)d_in[7];
    float* out = (float*)d_out;

    const int smem_bytes = (128 + 8 * MD + 2 * MW) * (int)sizeof(float); // 86,528 B
    cudaFuncSetAttribute(anode_kernel,
                         cudaFuncAttributeMaxDynamicSharedMemorySize, smem_bytes);

    const int grid = (BATCH + M - 1) / M;  // 147 CTAs ~ one per SM
    anode_kernel<<<grid, THREADS, smem_bytes>>>(ts, y0, W1, b1, W2, b2, W3, b3,
                                                out, out_size);
}

// round 5
// speedup vs baseline: 4.3608x; 4.3608x over previous
#include <cuda_runtime.h>

#define THREADS   256
#define MROWS     16          // batch rows per CTA
#define DIMV      128         // DATA + AUG
#define WIDTHV    256
#define DATAV     64
#define BATCH     2048
#define TSTEPS    128
#define SUBSTEPS  4
#define MD        (MROWS*DIMV)    // 2048
#define GRIDN     (BATCH/MROWS)   // 128

typedef unsigned long long ull;

// packed fp32x2 FMA: d = a*b + d  (Blackwell f32x2 pipe, 2 FMAs per issue slot)
#define FMA2(d, a, b) asm("fma.rn.f32x2 %0, %1, %2, %0;" : "+l"(d) : "l"(a), "l"(b))
#define PACK2(d, s)   asm("mov.b64 %0, {%1, %1};" : "=l"(d) : "r"(s))

// k-major (transposed) weight copies, written once per launch by a prep kernel
static __device__ float g_W1t[DIMV * WIDTHV];    // [k<128][j<256]
static __device__ float g_W2t[WIDTHV * WIDTHV];  // [k<256][j<256]
static __device__ float g_W3t[WIDTHV * DIMV];    // [k<256][j<128]

__global__ void transpose_weights(const float* __restrict__ W1,
                                  const float* __restrict__ W2,
                                  const float* __restrict__ W3)
{
    int stride = gridDim.x * blockDim.x;
    int i0 = blockIdx.x * blockDim.x + threadIdx.x;
    for (int t = i0; t < WIDTHV * DIMV; t += stride) {       // W1[j<256][k<128]
        int j = t >> 7, k = t & 127;
        g_W1t[k * WIDTHV + j] = W1[t];
    }
    for (int t = i0; t < WIDTHV * WIDTHV; t += stride) {     // W2[j<256][k<256]
        int j = t >> 8, k = t & 255;
        g_W2t[k * WIDTHV + j] = W2[t];
    }
    for (int t = i0; t < DIMV * WIDTHV; t += stride) {       // W3[j<128][k<256]
        int j = t >> 8, k = t & 255;
        g_W3t[k * DIMV + j] = W3[t];
    }
}

// ---------------------------------------------------------------------------
// One layer: out[j][m] = act( sum_k in[k][m] * Wt[k][j] + b[j] )
// Activations stored channel-major [k][16 rows] so row-pairs are f32x2-adjacent
// and every activation LDS is a warp broadcast (k is warp-uniform).
// K is split across G warp-groups (g = tid/CT); partials land in a padded
// (stride-65) smem buffer, reduced conflict-free by linear-indexed threads.
// ---------------------------------------------------------------------------
template<int N, int K, int G, bool RELU>
__device__ __forceinline__ void layer(const float* __restrict__ act,
                                      float* __restrict__ outp,
                                      const float* __restrict__ Wt,
                                      const float* __restrict__ bias,
                                      float* __restrict__ red, int tid)
{
    constexpr int CT = N / 4;      // column-threads (each owns 4 cols)
    constexpr int KR = K / G;      // k-range per group
    const int g  = tid / CT;       // warp-uniform
    const int ct = tid % CT;
    const int k0 = g * KR;

    ull acc[8][4];
#pragma unroll
    for (int p = 0; p < 8; ++p)
#pragma unroll
        for (int c = 0; c < 4; ++c) acc[p][c] = 0ull;

    const float4* wp = reinterpret_cast<const float4*>(Wt) + ct;  // lane-contiguous

#pragma unroll 2
    for (int k = k0; k < k0 + KR; ++k) {
        float4 w = __ldg(wp + k * CT);
        ull wd0, wd1, wd2, wd3;
        PACK2(wd0, __float_as_uint(w.x));
        PACK2(wd1, __float_as_uint(w.y));
        PACK2(wd2, __float_as_uint(w.z));
        PACK2(wd3, __float_as_uint(w.w));

        const ulonglong2* ap = reinterpret_cast<const ulonglong2*>(act + k * MROWS);
        ulonglong2 a0 = ap[0], a1 = ap[1], a2 = ap[2], a3 = ap[3];  // broadcast LDS
        ull av[8] = { a0.x, a0.y, a1.x, a1.y, a2.x, a2.y, a3.x, a3.y };

#pragma unroll
        for (int p = 0; p < 8; ++p) {
            FMA2(acc[p][0], av[p], wd0);
            FMA2(acc[p][1], av[p], wd1);
            FMA2(acc[p][2], av[p], wd2);
            FMA2(acc[p][3], av[p], wd3);
        }
    }

    // partials: writer-major layout, 65-float stride -> conflict-free scalar STS
    {
        float* rr = red + (g * CT + ct) * 65;
#pragma unroll
        for (int c = 0; c < 4; ++c)
#pragma unroll
            for (int p = 0; p < 8; ++p) {
                float2 v = *reinterpret_cast<float2*>(&acc[p][c]);
                rr[c * 16 + 2 * p]     = v.x;
                rr[c * 16 + 2 * p + 1] = v.y;
            }
    }
    __syncthreads();

    // reduce G partials, add bias, activation; outputs linear in [j][m]
    constexpr int NO = N * MROWS;
#pragma unroll
    for (int r = 0; r < NO / THREADS; ++r) {
        int o  = tid + r * THREADS;
        int jj = o >> 4, mm = o & 15;
        int base = (jj >> 2) * 65 + (jj & 3) * 16 + mm;
        float s = bias[jj];
#pragma unroll
        for (int gg = 0; gg < G; ++gg)
            s += red[gg * CT * 65 + base];
        if (RELU) s = fmaxf(s, 0.0f);
        outp[o] = s;
    }
    __syncthreads();
}

__device__ __forceinline__ void eval_f(const float* __restrict__ in,
                                       float* __restrict__ outk,
                                       float* __restrict__ h1, float* __restrict__ h2,
                                       float* __restrict__ red,
                                       const float* b1s, const float* b2s,
                                       const float* b3s, int tid)
{
    layer<WIDTHV, DIMV,   4, true >(in, h1, g_W1t, b1s, red, tid);
    layer<WIDTHV, WIDTHV, 4, true >(h1, h2, g_W2t, b2s, red, tid);
    layer<DIMV,   WIDTHV, 8, false>(h2, outk, g_W3t, b3s, red, tid);
}

// dst = y + dt * sum_s c[s] * ks[s]  (elementwise, [k][m] layout throughout)
template<int NS>
__device__ __forceinline__ void combine(float* __restrict__ dst,
                                        const float* __restrict__ y,
                                        const float* __restrict__ ks,
                                        float dt, const float* c, int tid)
{
#pragma unroll
    for (int r = 0; r < MD / THREADS; ++r) {
        int i = tid + r * THREADS;
        float v = y[i];
#pragma unroll
        for (int s = 0; s < NS; ++s)
            v = fmaf(dt * c[s], ks[s * MD + i], v);
        dst[i] = v;
    }
}

// write data channels (first 64) of all 16 rows for save time t
__device__ __forceinline__ void save_state(const float* __restrict__ y,
                                           float* __restrict__ out,
                                           int base, int t, int tid)
{
    int m  = tid & 15;
    int c4 = (tid >> 4) << 2;      // 16 groups * 4 = DATAV channels
    float4 o;
    o.x = y[(c4 + 0) * MROWS + m];
    o.y = y[(c4 + 1) * MROWS + m];
    o.z = y[(c4 + 2) * MROWS + m];
    o.w = y[(c4 + 3) * MROWS + m];
    *reinterpret_cast<float4*>(out + ((size_t)t * BATCH + base + m) * DATAV + c4) = o;
}

extern "C" __global__ void __launch_bounds__(THREADS, 1)
anode_kernel(const float* __restrict__ ts, const float* __restrict__ y0,
             const float* __restrict__ b1, const float* __restrict__ b2,
             const float* __restrict__ b3,
             float* __restrict__ out, int out_size)
{
    extern __shared__ float sm[];
    float* tssm = sm;                        // 128
    float* b1s  = tssm + 128;                // 256
    float* b2s  = b1s + 256;                 // 256
    float* b3s  = b2s + 256;                 // 128
    float* y    = b3s + 128;                 // MD  (2048)
    float* ytmp = y    + MD;                 // MD
    float* h1   = ytmp + MD;                 // 4096
    float* h2   = h1   + MROWS * WIDTHV;     // 4096
    float* ks   = h2   + MROWS * WIDTHV;     // 6*MD = 12288
    float* red  = ks   + 6 * MD;             // 16640

    const int tid  = threadIdx.x;
    const int base = blockIdx.x * MROWS;

    if (tid < TSTEPS) tssm[tid] = ts[tid];
    b1s[tid] = b1[tid];
    b2s[tid] = b2[tid];
    if (tid < DIMV) b3s[tid] = b3[tid];

    // load batch tile, transposing to [channel][m]
    {
        int m  = tid & 15;
        int cg = tid >> 4;
#pragma unroll
        for (int r = 0; r < 2; ++r) {
            int c4 = (cg + 16 * r) << 2;
            float4 v = *reinterpret_cast<const float4*>(y0 + (size_t)(base + m) * DIMV + c4);
            y[(c4 + 0) * MROWS + m] = v.x;
            y[(c4 + 1) * MROWS + m] = v.y;
            y[(c4 + 2) * MROWS + m] = v.z;
            y[(c4 + 3) * MROWS + m] = v.w;
        }
    }
    __syncthreads();

    save_state(y, out, base, 0, tid);

    // Dopri5 tableau
    const float c2[1] = {0.2f};
    const float c3[2] = {3.f/40.f, 9.f/40.f};
    const float c4_[3] = {44.f/45.f, -56.f/15.f, 32.f/9.f};
    const float c5[4] = {19372.f/6561.f, -25360.f/2187.f, 64448.f/6561.f, -212.f/729.f};
    const float c6[5] = {9017.f/3168.f, -355.f/33.f, 46732.f/5247.f, 49.f/176.f, -5103.f/18656.f};
    const float cb[6] = {35.f/384.f, 0.f, 500.f/1113.f, 125.f/192.f, -2187.f/6784.f, 11.f/84.f};

#pragma unroll 1
    for (int t = 1; t < TSTEPS; ++t) {
        float dt = (tssm[t] - tssm[t - 1]) * (1.0f / SUBSTEPS);
#pragma unroll 1
        for (int s = 0; s < SUBSTEPS; ++s) {
            eval_f(y,    ks + 0 * MD, h1, h2, red, b1s, b2s, b3s, tid);
            combine<1>(ytmp, y, ks, dt, c2, tid);   __syncthreads();
            eval_f(ytmp, ks + 1 * MD, h1, h2, red, b1s, b2s, b3s, tid);
            combine<2>(ytmp, y, ks, dt, c3, tid);   __syncthreads();
            eval_f(ytmp, ks + 2 * MD, h1, h2, red, b1s, b2s, b3s, tid);
            combine<3>(ytmp, y, ks, dt, c4_, tid);  __syncthreads();
            eval_f(ytmp, ks + 3 * MD, h1, h2, red, b1s, b2s, b3s, tid);
            combine<4>(ytmp, y, ks, dt, c5, tid);   __syncthreads();
            eval_f(ytmp, ks + 4 * MD, h1, h2, red, b1s, b2s, b3s, tid);
            combine<5>(ytmp, y, ks, dt, c6, tid);   __syncthreads();
            eval_f(ytmp, ks + 5 * MD, h1, h2, red, b1s, b2s, b3s, tid);
            combine<6>(y, y, ks, dt, cb, tid);      __syncthreads();
        }
        save_state(y, out, base, t, tid);
    }

    // second reference output: num_steps = (T-1)*SUBSTEPS = 508
    if (blockIdx.x == 0 && tid == 0) {
        const long long TOT = (long long)TSTEPS * BATCH * DATAV;
        for (long long i = TOT; i < (long long)out_size; ++i)
            out[i] = 508.0f;
    }
}

extern "C" void kernel_launch(void* const* d_in, const int* in_sizes, int n_in,
                              void* d_out, int out_size)
{
    const float* ts = (const float*)d_in[0];
    const float* y0 = (const float*)d_in[1];
    const float* W1 = (const float*)d_in[2];
    const float* b1 = (const float*)d_in[3];
    const float* W2 = (const float*)d_in[4];
    const float* b2 = (const float*)d_in[5];
    const float* W3 = (const float*)d_in[6];
    const float* b3 = (const float*)d_in[7];
    float* out = (float*)d_out;

    transpose_weights<<<256, 256>>>(W1, W2, W3);

    // smem: 128+256+256+128 + 2048 + 2048 + 4096 + 4096 + 12288 + 16640 floats
    const int smem_bytes = (768 + 2 * MD + 2 * MROWS * WIDTHV + 6 * MD + 16640)
                           * (int)sizeof(float);  // 167,936 B
    cudaFuncSetAttribute(anode_kernel,
                         cudaFuncAttributeMaxDynamicSharedMemorySize, smem_bytes);

    anode_kernel<<<GRIDN, THREADS, smem_bytes>>>(ts, y0, b1, b2, b3, out, out_size);
}

// round 7
// speedup vs baseline: 5.8368x; 1.3385x over previous
#include <cuda_runtime.h>

#define THREADS   512
#define MROWS     16          // batch rows per CTA
#define DIMV      128         // DATA + AUG
#define WIDTHV    256
#define DATAV     64
#define BATCH     2048
#define TSTEPS    128
#define SUBSTEPS  4
#define MD        (MROWS*DIMV)    // 2048
#define GRIDN     (BATCH/MROWS)   // 128

typedef unsigned long long ull;

// packed fp32x2 FMA: d = a*b + d
#define FMA2(d, a, b) asm("fma.rn.f32x2 %0, %1, %2, %0;" : "+l"(d) : "l"(a), "l"(b))
#define PACK2(d, s)   asm("mov.b64 %0, {%1, %1};" : "=l"(d) : "r"(s))

// k-major (transposed) weight copies (+ pad so unrolled prefetch can't fault)
static __device__ float g_W1t[DIMV * WIDTHV + 16];    // [k<128][j<256]
static __device__ float g_W2t[WIDTHV * WIDTHV + 16];  // [k<256][j<256]
static __device__ float g_W3t[WIDTHV * DIMV + 16];    // [k<256][j<128]

__global__ void transpose_weights(const float* __restrict__ W1,
                                  const float* __restrict__ W2,
                                  const float* __restrict__ W3)
{
    int stride = gridDim.x * blockDim.x;
    int i0 = blockIdx.x * blockDim.x + threadIdx.x;
    for (int t = i0; t < WIDTHV * DIMV; t += stride) {       // W1[j<256][k<128]
        int j = t >> 7, k = t & 127;
        g_W1t[k * WIDTHV + j] = W1[t];
    }
    for (int t = i0; t < WIDTHV * WIDTHV; t += stride) {     // W2[j<256][k<256]
        int j = t >> 8, k = t & 255;
        g_W2t[k * WIDTHV + j] = W2[t];
    }
    for (int t = i0; t < DIMV * WIDTHV; t += stride) {       // W3[j<128][k<256]
        int j = t >> 8, k = t & 255;
        g_W3t[k * DIMV + j] = W3[t];
    }
}

// ---------------------------------------------------------------------------
// One layer: out[j][m] = act( sum_k in[k][m] * Wt[k][j] + b[j] )
// Activations channel-major [k][16 rows]: every activation LDS is a warp
// broadcast (k warp-uniform) and row-pairs are f32x2-adjacent.
// TN=2 columns/thread; K split across G groups (g = tid/CT, warp-uniform).
// Partials: per-writer stride-33 smem layout (33 coprime 32 -> conflict-free
// scalar STS; reduce-phase reads are 32 contiguous words per warp).
// ---------------------------------------------------------------------------
template<int N, int K, int G, bool RELU>
__device__ __forceinline__ void layer(const float* __restrict__ act,
                                      float* __restrict__ outp,
                                      const float* __restrict__ Wt,
                                      const float* __restrict__ bias,
                                      float* __restrict__ red, int tid)
{
    constexpr int CT = N / 2;      // column-threads (each owns 2 cols)
    constexpr int KR = K / G;      // k-range per group
    static_assert(CT * G == THREADS, "thread mapping");
    const int g  = tid / CT;       // warp-uniform
    const int ct = tid % CT;
    const int k0 = g * KR;

    ull acc[8][2];
#pragma unroll
    for (int p = 0; p < 8; ++p) { acc[p][0] = 0ull; acc[p][1] = 0ull; }

    const float2* wp = reinterpret_cast<const float2*>(Wt) + ct;  // lane-contiguous

#pragma unroll 4
    for (int k = k0; k < k0 + KR; ++k) {
        float2 w = __ldg(wp + k * CT);
        ull wd0, wd1;
        PACK2(wd0, __float_as_uint(w.x));
        PACK2(wd1, __float_as_uint(w.y));

        const ulonglong2* ap = reinterpret_cast<const ulonglong2*>(act + k * MROWS);
        ulonglong2 a0 = ap[0], a1 = ap[1], a2 = ap[2], a3 = ap[3];  // broadcast LDS
        ull av[8] = { a0.x, a0.y, a1.x, a1.y, a2.x, a2.y, a3.x, a3.y };

#pragma unroll
        for (int p = 0; p < 8; ++p) {
            FMA2(acc[p][0], av[p], wd0);
            FMA2(acc[p][1], av[p], wd1);
        }
    }

    // partials: 32 floats per writer, stride-33 rows -> conflict-free scalar STS
    {
        float* rr = red + tid * 33;
#pragma unroll
        for (int c = 0; c < 2; ++c)
#pragma unroll
            for (int p = 0; p < 8; ++p) {
                float2 v = *reinterpret_cast<float2*>(&acc[p][c]);
                rr[c * 16 + 2 * p]     = v.x;
                rr[c * 16 + 2 * p + 1] = v.y;
            }
    }
    __syncthreads();

    // reduce G partials, add bias, activation; outputs linear in [j][m]
    constexpr int NO = N * MROWS;
#pragma unroll
    for (int r = 0; r < NO / THREADS; ++r) {
        int o  = tid + r * THREADS;
        int jj = o >> 4, mm = o & 15;
        int woff = (jj >> 1) * 33 + (jj & 1) * 16 + mm;
        float s = bias[jj];
#pragma unroll
        for (int gg = 0; gg < G; ++gg)
            s += red[gg * CT * 33 + woff];
        if (RELU) s = fmaxf(s, 0.0f);
        outp[o] = s;
    }
    __syncthreads();
}

__device__ __forceinline__ void eval_f(const float* __restrict__ in,
                                       float* __restrict__ outk,
                                       float* __restrict__ h1, float* __restrict__ h2,
                                       float* __restrict__ red,
                                       const float* b1s, const float* b2s,
                                       const float* b3s, int tid)
{
    layer<WIDTHV, DIMV,   4, true >(in, h1, g_W1t, b1s, red, tid);
    layer<WIDTHV, WIDTHV, 4, true >(h1, h2, g_W2t, b2s, red, tid);
    layer<DIMV,   WIDTHV, 8, false>(h2, outk, g_W3t, b3s, red, tid);
}

// dst = y + dt * sum_s c[s] * ks[s]  ([k][m] layout throughout)
template<int NS>
__device__ __forceinline__ void combine(float* __restrict__ dst,
                                        const float* __restrict__ y,
                                        const float* __restrict__ ks,
                                        float dt, const float* c, int tid)
{
#pragma unroll
    for (int r = 0; r < MD / THREADS; ++r) {
        int i = tid + r * THREADS;
        float v = y[i];
#pragma unroll
        for (int s = 0; s < NS; ++s)
            v = fmaf(dt * c[s], ks[s * MD + i], v);
        dst[i] = v;
    }
}

// write data channels (first 64) of all 16 rows for save time t
__device__ __forceinline__ void save_state(const float* __restrict__ y,
                                           float* __restrict__ out,
                                           int base, int t, int tid)
{
    int m  = tid & 15;
    int c2 = (tid >> 4) << 1;      // 32 groups * 2 = DATAV channels
    float2 o;
    o.x = y[(c2 + 0) * MROWS + m];
    o.y = y[(c2 + 1) * MROWS + m];
    *reinterpret_cast<float2*>(out + ((size_t)t * BATCH + base + m) * DATAV + c2) = o;
}

extern "C" __global__ void __launch_bounds__(THREADS, 1)
anode_kernel(const float* __restrict__ ts, const float* __restrict__ y0,
             const float* __restrict__ b1, const float* __restrict__ b2,
             const float* __restrict__ b3,
             float* __restrict__ out, int out_size)
{
    extern __shared__ float sm[];
    float* tssm = sm;                        // 128
    float* b1s  = tssm + 128;                // 256
    float* b2s  = b1s + 256;                 // 256
    float* b3s  = b2s + 256;                 // 128
    float* y    = b3s + 128;                 // MD  (2048)
    float* ytmp = y    + MD;                 // MD
    float* h1   = ytmp + MD;                 // 4096
    float* h2   = h1   + MROWS * WIDTHV;     // 4096
    float* ks   = h2   + MROWS * WIDTHV;     // 6*MD = 12288
    float* red  = ks   + 6 * MD;             // 512*33 = 16896

    const int tid  = threadIdx.x;
    const int base = blockIdx.x * MROWS;

    if (tid < TSTEPS) tssm[tid] = ts[tid];
    if (tid < WIDTHV) { b1s[tid] = b1[tid]; b2s[tid] = b2[tid]; }
    if (tid < DIMV)   b3s[tid] = b3[tid];

    // load batch tile, transposing to [channel][m]
    {
        int m  = tid & 15;
        int c4 = (tid >> 4) << 2;   // 32 groups * 4 = DIMV channels
        float4 v = *reinterpret_cast<const float4*>(y0 + (size_t)(base + m) * DIMV + c4);
        y[(c4 + 0) * MROWS + m] = v.x;
        y[(c4 + 1) * MROWS + m] = v.y;
        y[(c4 + 2) * MROWS + m] = v.z;
        y[(c4 + 3) * MROWS + m] = v.w;
    }
    __syncthreads();

    save_state(y, out, base, 0, tid);

    // Dopri5 tableau
    const float c2_[1] = {0.2f};
    const float c3_[2] = {3.f/40.f, 9.f/40.f};
    const float c4_[3] = {44.f/45.f, -56.f/15.f, 32.f/9.f};
    const float c5_[4] = {19372.f/6561.f, -25360.f/2187.f, 64448.f/6561.f, -212.f/729.f};
    const float c6_[5] = {9017.f/3168.f, -355.f/33.f, 46732.f/5247.f, 49.f/176.f, -5103.f/18656.f};
    const float cb_[6] = {35.f/384.f, 0.f, 500.f/1113.f, 125.f/192.f, -2187.f/6784.f, 11.f/84.f};

#pragma unroll 1
    for (int t = 1; t < TSTEPS; ++t) {
        float dt = (tssm[t] - tssm[t - 1]) * (1.0f / SUBSTEPS);
#pragma unroll 1
        for (int s = 0; s < SUBSTEPS; ++s) {
            eval_f(y,    ks + 0 * MD, h1, h2, red, b1s, b2s, b3s, tid);
            combine<1>(ytmp, y, ks, dt, c2_, tid);  __syncthreads();
            eval_f(ytmp, ks + 1 * MD, h1, h2, red, b1s, b2s, b3s, tid);
            combine<2>(ytmp, y, ks, dt, c3_, tid);  __syncthreads();
            eval_f(ytmp, ks + 2 * MD, h1, h2, red, b1s, b2s, b3s, tid);
            combine<3>(ytmp, y, ks, dt, c4_, tid);  __syncthreads();
            eval_f(ytmp, ks + 3 * MD, h1, h2, red, b1s, b2s, b3s, tid);
            combine<4>(ytmp, y, ks, dt, c5_, tid);  __syncthreads();
            eval_f(ytmp, ks + 4 * MD, h1, h2, red, b1s, b2s, b3s, tid);
            combine<5>(ytmp, y, ks, dt, c6_, tid);  __syncthreads();
            eval_f(ytmp, ks + 5 * MD, h1, h2, red, b1s, b2s, b3s, tid);
            combine<6>(y, y, ks, dt, cb_, tid);     __syncthreads();
        }
        save_state(y, out, base, t, tid);
    }

    // second reference output: num_steps = (T-1)*SUBSTEPS = 508
    if (blockIdx.x == 0 && tid == 0) {
        const long long TOT = (long long)TSTEPS * BATCH * DATAV;
        for (long long i = TOT; i < (long long)out_size; ++i)
            out[i] = 508.0f;
    }
}

extern "C" void kernel_launch(void* const* d_in, const int* in_sizes, int n_in,
                              void* d_out, int out_size)
{
    const float* ts = (const float*)d_in[0];
    const float* y0 = (const float*)d_in[1];
    const float* W1 = (const float*)d_in[2];
    const float* b1 = (const float*)d_in[3];
    const float* W2 = (const float*)d_in[4];
    const float* b2 = (const float*)d_in[5];
    const float* W3 = (const float*)d_in[6];
    const float* b3 = (const float*)d_in[7];
    float* out = (float*)d_out;

    transpose_weights<<<256, 256>>>(W1, W2, W3);

    // smem floats: 768 + 2*2048 + 2*4096 + 12288 + 16896 = 42240 -> 168,960 B
    const int smem_bytes = (768 + 2 * MD + 2 * MROWS * WIDTHV + 6 * MD + THREADS * 33)
                           * (int)sizeof(float);
    cudaFuncSetAttribute(anode_kernel,
                         cudaFuncAttributeMaxDynamicSharedMemorySize, smem_bytes);

    anode_kernel<<<GRIDN, THREADS, smem_bytes>>>(ts, y0, b1, b2, b3, out, out_size);
}